// round 3
// baseline (speedup 1.0000x reference)
#include <cuda_runtime.h>
#include <cuda_bf16.h>

// OneHotEncoder: per-row histogram of tokens [256, 2048] -> counts [256, 32000] f32,
// skipping pad_idx=0. `lengths` input is unused by the reference.
//
// Strategy: one CTA per row. Shared-memory histogram with two u16 counters packed
// per u32 word (max per-bin count = 2048 < 65536, so atomicAdd with increment
// 1 or 1<<16 can never carry across the packed boundary). 64 KB smem -> 2 CTAs/SM
// -> all 256 CTAs run in a single wave on 148 SMs. Output written exactly once,
// vectorized as float4.

#define VOCAB   32000
#define SEQ_T   2048
#define NWORDS  (VOCAB / 2)       // 16000 packed u32 words
#define THREADS 512
#define SMEM_BYTES (NWORDS * sizeof(unsigned int))  // 64000 bytes

__global__ __launch_bounds__(THREADS, 2)
void onehot_hist_kernel(const int* __restrict__ tokens,
                        float* __restrict__ out)
{
    extern __shared__ unsigned int hist[];   // NWORDS words = 32000 u16 counters

    const int row = blockIdx.x;
    const int tid = threadIdx.x;

    // --- zero the shared histogram (16000 words / 512 threads = 31.25 iters) ---
    #pragma unroll 8
    for (int i = tid; i < NWORDS; i += THREADS) {
        hist[i] = 0u;
    }
    __syncthreads();

    // --- accumulate: vectorized int4 token loads, shared atomics ---
    const int4* tok4 = reinterpret_cast<const int4*>(tokens + (size_t)row * SEQ_T);
    #pragma unroll
    for (int i = tid; i < SEQ_T / 4; i += THREADS) {   // 1 iter per thread
        int4 t = tok4[i];
        if (t.x != 0) atomicAdd(&hist[(unsigned)t.x >> 1], 1u << (((unsigned)t.x & 1u) << 4));
        if (t.y != 0) atomicAdd(&hist[(unsigned)t.y >> 1], 1u << (((unsigned)t.y & 1u) << 4));
        if (t.z != 0) atomicAdd(&hist[(unsigned)t.z >> 1], 1u << (((unsigned)t.z & 1u) << 4));
        if (t.w != 0) atomicAdd(&hist[(unsigned)t.w >> 1], 1u << (((unsigned)t.w & 1u) << 4));
    }
    __syncthreads();

    // --- unpack + write out: 2 packed words -> float4, STG.128 ---
    float4* out4 = reinterpret_cast<float4*>(out + (size_t)row * VOCAB);
    const uint2* hist2 = reinterpret_cast<const uint2*>(hist);
    #pragma unroll 4
    for (int i = tid; i < NWORDS / 2; i += THREADS) {  // 8000 / 512 = 15.6 iters
        uint2 w = hist2[i];
        float4 v;
        v.x = (float)(w.x & 0xFFFFu);
        v.y = (float)(w.x >> 16);
        v.z = (float)(w.y & 0xFFFFu);
        v.w = (float)(w.y >> 16);
        out4[i] = v;
    }
}

extern "C" void kernel_launch(void* const* d_in, const int* in_sizes, int n_in,
                              void* d_out, int out_size)
{
    const int* tokens = (const int*)d_in[0];   // [256, 2048] int32
    // d_in[1] = lengths, unused by the reference computation.
    float* out = (float*)d_out;                // [256, 32000] f32

    const int batch = in_sizes[0] / SEQ_T;     // 256

    static bool attr_set = false;
    // cudaFuncSetAttribute is a host-side config call (no stream work, no alloc);
    // it is idempotent — calling it on every invocation keeps kernel_launch
    // deterministic and capture-safe.
    cudaFuncSetAttribute(onehot_hist_kernel,
                         cudaFuncAttributeMaxDynamicSharedMemorySize,
                         SMEM_BYTES);
    (void)attr_set;

    onehot_hist_kernel<<<batch, THREADS, SMEM_BYTES>>>(tokens, out);
}